// round 4
// baseline (speedup 1.0000x reference)
#include <cuda_runtime.h>

// Shapes fixed by the problem: bz=4, C=32, H=W=256, NF=12 focal slices.
#define NF    12
#define BZ    4
#define C_    32
#define HW    65536           // 256*256
#define CHW   (C_ * HW)       // 2,097,152
#define CHW4  (CHW / 4)       // 524,288 = 2^19
#define HW4   (HW / 4)        // 16,384

#define BPB   512             // reduction blocks along the chunk axis
#define TPB   256
#define CHUNK (CHW4 / BPB)    // 1024 float4 per block (4 iters/thread)

// Scratch (no allocation allowed).
__device__ float    g_part[BZ * NF * BPB];   // 96 KB partials
__device__ int      g_sel[2 * BZ];
__device__ unsigned g_count = 0;             // last-block counter (self-resetting)

// ---------------------------------------------------------------------------
// Kernel 1: each block owns one (b, chunk), accumulates ALL 12 focal MAEs
// (14 independent 16B loads in flight per iteration). Last block to finish
// performs the final double-precision reduction + pair selection.
// grid = (BPB, BZ).
// ---------------------------------------------------------------------------
__global__ __launch_bounds__(TPB) void k_reduce(const float* __restrict__ x,
                                                const float* __restrict__ xf,
                                                const float* __restrict__ sal) {
    const int b    = blockIdx.y;
    const int base = blockIdx.x * CHUNK;

    const float4* __restrict__ xp = (const float4*)(x   + (size_t)b * CHW);
    const float4* __restrict__ sp = (const float4*)(sal + (size_t)b * HW);
    const float4* __restrict__ fbase = (const float4*)(xf + (size_t)b * CHW);
    const size_t fstride4 = (size_t)BZ * CHW4;   // float4 stride between focals

    float acc[NF];
#pragma unroll
    for (int f = 0; f < NF; ++f) acc[f] = 0.f;

    for (int i = threadIdx.x; i < CHUNK; i += TPB) {
        const int v = base + i;
        const float4 a = xp[v];
        const float4 s = sp[v & (HW4 - 1)];       // sal broadcast over channels
        float4 g[NF];
#pragma unroll
        for (int f = 0; f < NF; ++f) g[f] = __ldcs(fbase + f * fstride4 + v);
#pragma unroll
        for (int f = 0; f < NF; ++f) {
            acc[f] += fabsf(s.x * (a.x - g[f].x));
            acc[f] += fabsf(s.y * (a.y - g[f].y));
            acc[f] += fabsf(s.z * (a.z - g[f].z));
            acc[f] += fabsf(s.w * (a.w - g[f].w));
        }
    }

    // Warp shuffle reduce each accumulator, then combine warps in shared.
    const int lane = threadIdx.x & 31;
    const int warp = threadIdx.x >> 5;
#pragma unroll
    for (int f = 0; f < NF; ++f) {
        float v = acc[f];
#pragma unroll
        for (int o = 16; o > 0; o >>= 1)
            v += __shfl_down_sync(0xffffffffu, v, o);
        acc[f] = v;
    }
    __shared__ float sh[TPB / 32][NF];
    if (lane == 0) {
#pragma unroll
        for (int f = 0; f < NF; ++f) sh[warp][f] = acc[f];
    }
    __syncthreads();
    if (threadIdx.x < NF) {
        const int f = threadIdx.x;
        float s = 0.f;
#pragma unroll
        for (int w = 0; w < TPB / 32; ++w) s += sh[w][f];
        g_part[(b * NF + f) * BPB + blockIdx.x] = s;
    }

    // ---- last-block-done: run selection in whichever block finishes last ----
    __shared__ bool amLast;
    if (threadIdx.x == 0) {
        __threadfence();
        amLast = (atomicAdd(&g_count, 1u) == (unsigned)(BPB * BZ) - 1u);
    }
    __syncthreads();
    if (!amLast) return;

    // Final reduction in double, fixed order: 4 threads per (b,f), 128 each.
    __shared__ double part4[BZ * NF][4];
    __shared__ double mae[BZ * NF];
    const int t = threadIdx.x;
    if (t < BZ * NF * 4) {
        const int bf = t >> 2;
        const int g  = t & 3;
        double s = 0.0;
#pragma unroll 8
        for (int q = 0; q < BPB / 4; ++q)
            s += (double)__ldcg(&g_part[bf * BPB + g * (BPB / 4) + q]);
        part4[bf][g] = s;
    }
    __syncthreads();
    if (t < BZ * NF)
        mae[t] = ((part4[t][0] + part4[t][1]) + part4[t][2]) + part4[t][3];
    __syncthreads();
    if (t < BZ) {
        double best = -1.0;
        int bi = 0, bj = 0;
        for (int i = 0; i < NF; ++i)
            for (int j = i + 1; j < NF; ++j) {
                const double d = mae[t * NF + i] - mae[t * NF + j];
                const double v = d * d;          // 0.5 factor irrelevant for order
                if (v > best) { best = v; bi = i; bj = j; }
            }
        if (!(best > 0.0)) { bi = 0; bj = 0; }
        g_sel[t]      = bi;
        g_sel[BZ + t] = bj;
    }
    if (t == 0) g_count = 0;   // reset for next graph replay
}

// ---------------------------------------------------------------------------
// Kernel 2: gather-copy. Two-phase: batch 8 independent loads into registers,
// then 8 write-back stores. Block chunk = 2048 float4, divides CHW4.
// ---------------------------------------------------------------------------
#define CPT 8
__global__ __launch_bounds__(TPB) void k_copy(const float* __restrict__ xf,
                                              float* __restrict__ out) {
    const long long q0 = (long long)blockIdx.x * (TPB * CPT);
    const int r     = (int)(q0 >> 19);      // output row 0..7, constant per block
    const int b     = r & (BZ - 1);
    const int which = r >> 2;
    const int f     = g_sel[which * BZ + b];

    const float4* __restrict__ src = (const float4*)(xf + ((size_t)f * BZ + b) * CHW);
    float4* __restrict__ dst = (float4*)out;

    const int n0 = (int)(q0 & (CHW4 - 1)) + threadIdx.x;
    float4 v[CPT];
#pragma unroll
    for (int c = 0; c < CPT; ++c) v[c] = __ldcg(&src[n0 + c * TPB]);
#pragma unroll
    for (int c = 0; c < CPT; ++c) dst[q0 + threadIdx.x + c * TPB] = v[c];
}

// ---------------------------------------------------------------------------
extern "C" void kernel_launch(void* const* d_in, const int* in_sizes, int n_in,
                              void* d_out, int out_size) {
    const float* x   = (const float*)d_in[0];   // [4,32,256,256]
    const float* xf  = (const float*)d_in[1];   // [48,32,256,256]
    const float* sal = (const float*)d_in[2];   // [4,1,256,256]
    float*       out = (float*)d_out;           // [8,32,256,256]

    dim3 gridR(BPB, BZ);
    k_reduce<<<gridR, TPB>>>(x, xf, sal);
    const unsigned blocksC = (unsigned)((2LL * BZ * CHW4) / (TPB * CPT)); // 2048
    k_copy<<<blocksC, TPB>>>(xf, out);
}

// round 5
// speedup vs baseline: 1.0642x; 1.0642x over previous
#include <cuda_runtime.h>

// Shapes fixed by the problem: bz=4, C=32, H=W=256, NF=12 focal slices.
#define NF    12
#define BZ    4
#define C_    32
#define HW    65536            // 256*256
#define CHW   (C_ * HW)        // 2,097,152 floats per slice
#define CHW4  (CHW / 4)        // 524,288 float4 = 2^19
#define HW4   (HW / 4)         // 16,384

#define NBLK  296              // 2 blocks per SM on 148 SMs -> fully resident
#define TPB   256
#define NCH   148              // reduce chunks per batch
#define TLEN  3543             // ceil(CHW4 / NCH); last chunk ragged
#define TILES (BZ * NCH)       // 592 = 2 * NBLK -> perfectly balanced

#define NCOPY 4096             // copy chunks of 1024 float4 (divides CHW4)
#define CPT   4

// Scratch (no allocation allowed). Counters self-reset each launch.
__device__ float    g_part[BZ * NF * NCH];
__device__ int      g_sel[2 * BZ];
__device__ unsigned g_cnt  = 0;   // reduce-done block counter
__device__ unsigned g_ready = 0;  // selection-published flag
__device__ unsigned g_cnt2 = 0;   // copy-done block counter (for reset)

__global__ __launch_bounds__(TPB, 2) void k_all(const float* __restrict__ x,
                                                const float* __restrict__ xf,
                                                const float* __restrict__ sal,
                                                float* __restrict__ out) {
    const int tid  = threadIdx.x;
    const int lane = tid & 31;
    const int warp = tid >> 5;
    __shared__ float sh[TPB / 32][NF];

    // ===================== Phase A: reduction (2 tiles/block) ==============
    for (int t = blockIdx.x; t < TILES; t += NBLK) {
        const int b     = t / NCH;
        const int c     = t % NCH;
        const int start = c * TLEN;
        const int end   = (start + TLEN < CHW4) ? start + TLEN : CHW4;

        const float4* __restrict__ xp = (const float4*)(x   + (size_t)b * CHW);
        const float4* __restrict__ sp = (const float4*)(sal + (size_t)b * HW);
        const float4* __restrict__ fb = (const float4*)(xf  + (size_t)b * CHW);
        const size_t fstride4 = (size_t)BZ * CHW4;    // float4 stride between focals

        float acc[NF];
#pragma unroll
        for (int f = 0; f < NF; ++f) acc[f] = 0.f;

        for (int i = start + tid; i < end; i += TPB) {
            const float4 a = xp[i];
            const float4 s = sp[i & (HW4 - 1)];       // sal broadcast over channels
            float4 g[NF];
#pragma unroll
            for (int f = 0; f < NF; ++f) g[f] = __ldcs(fb + f * fstride4 + i);
#pragma unroll
            for (int f = 0; f < NF; ++f) {
                acc[f] += fabsf(s.x * (a.x - g[f].x));
                acc[f] += fabsf(s.y * (a.y - g[f].y));
                acc[f] += fabsf(s.z * (a.z - g[f].z));
                acc[f] += fabsf(s.w * (a.w - g[f].w));
            }
        }

#pragma unroll
        for (int f = 0; f < NF; ++f) {
            float v = acc[f];
#pragma unroll
            for (int o = 16; o > 0; o >>= 1)
                v += __shfl_down_sync(0xffffffffu, v, o);
            acc[f] = v;
        }
        if (lane == 0) {
#pragma unroll
            for (int f = 0; f < NF; ++f) sh[warp][f] = acc[f];
        }
        __syncthreads();
        if (tid < NF) {
            float s = 0.f;
#pragma unroll
            for (int w = 0; w < TPB / 32; ++w) s += sh[w][tid];
            g_part[(b * NF + tid) * NCH + c] = s;
        }
        __syncthreads();   // sh reused next tile
    }

    // ===================== Selection in the last-arriving block ============
    __threadfence();
    __shared__ bool amLast;
    if (tid == 0)
        amLast = (atomicAdd(&g_cnt, 1u) == (unsigned)NBLK - 1u);
    __syncthreads();

    if (amLast) {
        __shared__ double part4[BZ * NF][4];
        __shared__ double mae[BZ * NF];
        if (tid < BZ * NF * 4) {
            const int bf = tid >> 2;
            const int g  = tid & 3;
            double s = 0.0;
            for (int q = 0; q < NCH / 4; ++q)          // 148 = 4 * 37
                s += (double)__ldcg(&g_part[bf * NCH + g * (NCH / 4) + q]);
            part4[bf][g] = s;
        }
        __syncthreads();
        if (tid < BZ * NF)
            mae[tid] = ((part4[tid][0] + part4[tid][1]) + part4[tid][2]) + part4[tid][3];
        __syncthreads();
        if (tid < BZ) {
            double best = -1.0;
            int bi = 0, bj = 0;
            for (int i = 0; i < NF; ++i)
                for (int j = i + 1; j < NF; ++j) {
                    const double d = mae[tid * NF + i] - mae[tid * NF + j];
                    const double v = d * d;            // 0.5 irrelevant for ordering
                    if (v > best) { best = v; bi = i; bj = j; }
                }
            if (!(best > 0.0)) { bi = 0; bj = 0; }
            g_sel[tid]      = bi;
            g_sel[BZ + tid] = bj;
        }
        __syncthreads();
        if (tid == 0) {
            __threadfence();
            atomicExch(&g_ready, 1u);
        }
    }

    // ===================== Wait for selection ==============================
    if (tid == 0) {
        while (atomicAdd(&g_ready, 0u) == 0u) __nanosleep(128);
    }
    __syncthreads();
    __threadfence();

    // ===================== Phase B: gather-copy ============================
    float4* __restrict__ dst = (float4*)out;
    for (int c = blockIdx.x; c < NCOPY; c += NBLK) {
        const long long q0 = (long long)c * (TPB * CPT);    // 1024 float4 chunk
        const int r     = (int)(q0 >> 19);                  // output row 0..7
        const int b     = r & (BZ - 1);
        const int which = r >> 2;
        const int f     = __ldcg(&g_sel[which * BZ + b]);

        const float4* __restrict__ src =
            (const float4*)(xf + ((size_t)f * BZ + b) * CHW);
        const int n0 = (int)(q0 & (CHW4 - 1)) + tid;

        float4 v[CPT];
#pragma unroll
        for (int k = 0; k < CPT; ++k) v[k] = __ldcg(&src[n0 + k * TPB]);
#pragma unroll
        for (int k = 0; k < CPT; ++k) dst[q0 + tid + k * TPB] = v[k];
    }

    // ===================== Reset counters for next graph replay ============
    if (tid == 0) {
        if (atomicAdd(&g_cnt2, 1u) == (unsigned)NBLK - 1u) {
            g_cnt   = 0;
            g_ready = 0;
            g_cnt2  = 0;
        }
    }
}

// ---------------------------------------------------------------------------
extern "C" void kernel_launch(void* const* d_in, const int* in_sizes, int n_in,
                              void* d_out, int out_size) {
    const float* x   = (const float*)d_in[0];   // [4,32,256,256]
    const float* xf  = (const float*)d_in[1];   // [48,32,256,256]
    const float* sal = (const float*)d_in[2];   // [4,1,256,256]
    float*       out = (float*)d_out;           // [8,32,256,256]

    k_all<<<NBLK, TPB>>>(x, xf, sal, out);
}

// round 6
// speedup vs baseline: 1.0651x; 1.0009x over previous
#include <cuda_runtime.h>

// Shapes fixed by the problem: bz=4, C=32, H=W=256, NF=12 focal slices.
#define NF    12
#define NG    6               // focal loads per inner group (2 groups/iter)
#define BZ    4
#define C_    32
#define HW    65536           // 256*256
#define CHW   (C_ * HW)       // 2,097,152
#define CHW4  (CHW / 4)       // 524,288 = 2^19
#define HW4   (HW / 4)        // 16,384

#define BPB   128             // reduction blocks along the chunk axis
#define TPB   256
#define CHUNK (CHW4 / BPB)    // 4096 float4 per block (16 iters/thread)

// Scratch (no allocation allowed).
__device__ float    g_part[BZ * NF * BPB];
__device__ int      g_sel[2 * BZ];
__device__ unsigned g_cnt = 0;    // last-block counter (reset by last block)

// ---------------------------------------------------------------------------
// Kernel 1: reduce over all 12 focals per (b, chunk); loads split into two
// groups of 6 to keep live registers < 64 (4 blocks/SM). The last block to
// finish performs the final double-precision reduction + pair selection.
// grid = (BPB, BZ).
// ---------------------------------------------------------------------------
__global__ __launch_bounds__(TPB, 4) void k_reduce(const float* __restrict__ x,
                                                   const float* __restrict__ xf,
                                                   const float* __restrict__ sal) {
    const int b    = blockIdx.y;
    const int base = blockIdx.x * CHUNK;

    const float4* __restrict__ xp = (const float4*)(x   + (size_t)b * CHW);
    const float4* __restrict__ sp = (const float4*)(sal + (size_t)b * HW);
    const float4* __restrict__ fb = (const float4*)(xf  + (size_t)b * CHW);
    const size_t fstride4 = (size_t)BZ * CHW4;   // float4 stride between focals

    float acc[NF];
#pragma unroll
    for (int f = 0; f < NF; ++f) acc[f] = 0.f;

    for (int i = threadIdx.x; i < CHUNK; i += TPB) {
        const int v = base + i;
        const float4 a = xp[v];
        const float4 s = sp[v & (HW4 - 1)];       // sal broadcast over channels
        float4 g[NG];
        // group 0: focals 0..5
#pragma unroll
        for (int k = 0; k < NG; ++k) g[k] = __ldcs(fb + k * fstride4 + v);
#pragma unroll
        for (int k = 0; k < NG; ++k) {
            acc[k] += fabsf(s.x * (a.x - g[k].x));
            acc[k] += fabsf(s.y * (a.y - g[k].y));
            acc[k] += fabsf(s.z * (a.z - g[k].z));
            acc[k] += fabsf(s.w * (a.w - g[k].w));
        }
        // group 1: focals 6..11 (reuses g registers)
#pragma unroll
        for (int k = 0; k < NG; ++k) g[k] = __ldcs(fb + (k + NG) * fstride4 + v);
#pragma unroll
        for (int k = 0; k < NG; ++k) {
            acc[NG + k] += fabsf(s.x * (a.x - g[k].x));
            acc[NG + k] += fabsf(s.y * (a.y - g[k].y));
            acc[NG + k] += fabsf(s.z * (a.z - g[k].z));
            acc[NG + k] += fabsf(s.w * (a.w - g[k].w));
        }
    }

    // Warp shuffle reduce each accumulator, then combine warps in shared.
    const int lane = threadIdx.x & 31;
    const int warp = threadIdx.x >> 5;
#pragma unroll
    for (int f = 0; f < NF; ++f) {
        float v = acc[f];
#pragma unroll
        for (int o = 16; o > 0; o >>= 1)
            v += __shfl_down_sync(0xffffffffu, v, o);
        acc[f] = v;
    }
    __shared__ float sh[TPB / 32][NF];
    if (lane == 0) {
#pragma unroll
        for (int f = 0; f < NF; ++f) sh[warp][f] = acc[f];
    }
    __syncthreads();
    if (threadIdx.x < NF) {
        const int f = threadIdx.x;
        float s = 0.f;
#pragma unroll
        for (int w = 0; w < TPB / 32; ++w) s += sh[w][f];
        g_part[(b * NF + f) * BPB + blockIdx.x] = s;
    }

    // ---- last-block-done: selection runs in whichever block finishes last --
    __shared__ bool amLast;
    if (threadIdx.x == 0) {
        __threadfence();
        amLast = (atomicAdd(&g_cnt, 1u) == (unsigned)(BPB * BZ) - 1u);
    }
    __syncthreads();
    if (!amLast) return;

    __shared__ double part4[BZ * NF][4];
    __shared__ double mae[BZ * NF];
    const int t = threadIdx.x;
    if (t < BZ * NF * 4) {
        const int bf = t >> 2;
        const int g  = t & 3;
        double s = 0.0;
#pragma unroll 8
        for (int q = 0; q < BPB / 4; ++q)
            s += (double)__ldcg(&g_part[bf * BPB + g * (BPB / 4) + q]);
        part4[bf][g] = s;
    }
    __syncthreads();
    if (t < BZ * NF)
        mae[t] = ((part4[t][0] + part4[t][1]) + part4[t][2]) + part4[t][3];
    __syncthreads();
    if (t < BZ) {
        double best = -1.0;
        int bi = 0, bj = 0;
        for (int i = 0; i < NF; ++i)
            for (int j = i + 1; j < NF; ++j) {
                const double d = mae[t * NF + i] - mae[t * NF + j];
                const double v = d * d;          // 0.5 factor irrelevant for order
                if (v > best) { best = v; bi = i; bj = j; }
            }
        if (!(best > 0.0)) { bi = 0; bj = 0; }
        g_sel[t]      = bi;
        g_sel[BZ + t] = bj;
    }
    if (t == 0) g_cnt = 0;    // reset for next graph replay
}

// ---------------------------------------------------------------------------
// Kernel 2: gather-copy. Batch 8 independent streaming loads into registers,
// then 8 write-back stores. Block chunk = 2048 float4, divides CHW4.
// ---------------------------------------------------------------------------
#define CPT 8
__global__ __launch_bounds__(TPB) void k_copy(const float* __restrict__ xf,
                                              float* __restrict__ out) {
    const long long q0 = (long long)blockIdx.x * (TPB * CPT);
    const int r     = (int)(q0 >> 19);      // output row 0..7, constant per block
    const int b     = r & (BZ - 1);
    const int which = r >> 2;
    const int f     = g_sel[which * BZ + b];

    const float4* __restrict__ src = (const float4*)(xf + ((size_t)f * BZ + b) * CHW);
    float4* __restrict__ dst = (float4*)out;

    const int n0 = (int)(q0 & (CHW4 - 1)) + threadIdx.x;
    float4 v[CPT];
#pragma unroll
    for (int c = 0; c < CPT; ++c) v[c] = __ldcs(&src[n0 + c * TPB]);
#pragma unroll
    for (int c = 0; c < CPT; ++c) dst[q0 + threadIdx.x + c * TPB] = v[c];
}

// ---------------------------------------------------------------------------
extern "C" void kernel_launch(void* const* d_in, const int* in_sizes, int n_in,
                              void* d_out, int out_size) {
    const float* x   = (const float*)d_in[0];   // [4,32,256,256]
    const float* xf  = (const float*)d_in[1];   // [48,32,256,256]
    const float* sal = (const float*)d_in[2];   // [4,1,256,256]
    float*       out = (float*)d_out;           // [8,32,256,256]

    dim3 gridR(BPB, BZ);
    k_reduce<<<gridR, TPB>>>(x, xf, sal);
    const unsigned blocksC = (unsigned)((2LL * BZ * CHW4) / (TPB * CPT)); // 2048
    k_copy<<<blocksC, TPB>>>(xf, out);
}

// round 7
// speedup vs baseline: 1.0982x; 1.0310x over previous
#include <cuda_runtime.h>

// Shapes fixed by the problem: bz=4, C=32, H=W=256, NF=12 focal slices.
#define NF    12
#define BZ    4
#define C_    32
#define HW    65536           // 256*256
#define CHW   (C_ * HW)       // 2,097,152
#define CHW4  (CHW / 4)       // 524,288 = 2^19
#define HW4   (HW / 4)        // 16,384

#define BPB   128             // reduction blocks along the chunk axis
#define TPB   256
#define CHUNK (CHW4 / BPB)    // 4096 float4 per block (16 iters/thread)

// Scratch (no allocation allowed).
__device__ float    g_part[BZ * NF * BPB];
__device__ int      g_sel[2 * BZ];
__device__ unsigned g_cnt = 0;    // last-block counter (reset by last block)

// ---------------------------------------------------------------------------
// Selection tail: runs in ONE block (the last to finish the reduction).
// __noinline__ so its register/shared demands do not perturb the register
// allocation of the hot reduction loop.
// ---------------------------------------------------------------------------
__device__ __noinline__ void select_tail() {
    __shared__ double part4[BZ * NF][4];
    __shared__ double mae[BZ * NF];
    const int t = threadIdx.x;
    if (t < BZ * NF * 4) {
        const int bf = t >> 2;
        const int g  = t & 3;
        double s = 0.0;
#pragma unroll 8
        for (int q = 0; q < BPB / 4; ++q)
            s += (double)__ldcg(&g_part[bf * BPB + g * (BPB / 4) + q]);
        part4[bf][g] = s;
    }
    __syncthreads();
    if (t < BZ * NF)
        mae[t] = ((part4[t][0] + part4[t][1]) + part4[t][2]) + part4[t][3];
    __syncthreads();
    if (t < BZ) {
        double best = -1.0;
        int bi = 0, bj = 0;
        for (int i = 0; i < NF; ++i)
            for (int j = i + 1; j < NF; ++j) {
                const double d = mae[t * NF + i] - mae[t * NF + j];
                const double v = d * d;          // 0.5 factor irrelevant for order
                if (v > best) { best = v; bi = i; bj = j; }
            }
        if (!(best > 0.0)) { bi = 0; bj = 0; }
        g_sel[t]      = bi;
        g_sel[BZ + t] = bj;
    }
    if (t == 0) g_cnt = 0;    // reset for next graph replay
}

// ---------------------------------------------------------------------------
// Kernel 1: each block owns one (b, chunk) and accumulates ALL 12 focal MAEs
// (14 independent 16B loads in flight per iteration). Identical hot loop to
// the best-measured R2 kernel (68.7us @ 81% DRAM).
// grid = (BPB, BZ).
// ---------------------------------------------------------------------------
__global__ __launch_bounds__(TPB, 2) void k_reduce(const float* __restrict__ x,
                                                   const float* __restrict__ xf,
                                                   const float* __restrict__ sal) {
    const int b    = blockIdx.y;
    const int base = blockIdx.x * CHUNK;

    const float4* __restrict__ xp = (const float4*)(x   + (size_t)b * CHW);
    const float4* __restrict__ sp = (const float4*)(sal + (size_t)b * HW);

    const float4* __restrict__ fp[NF];
#pragma unroll
    for (int f = 0; f < NF; ++f)
        fp[f] = (const float4*)(xf + ((size_t)f * BZ + b) * CHW);

    float acc[NF];
#pragma unroll
    for (int f = 0; f < NF; ++f) acc[f] = 0.f;

    for (int i = threadIdx.x; i < CHUNK; i += TPB) {
        const int v = base + i;
        const float4 a = xp[v];
        const float4 s = sp[v & (HW4 - 1)];       // sal broadcast over channels
        float4 g[NF];
#pragma unroll
        for (int f = 0; f < NF; ++f) g[f] = __ldcs(&fp[f][v]);
#pragma unroll
        for (int f = 0; f < NF; ++f) {
            acc[f] += fabsf(s.x * (a.x - g[f].x));
            acc[f] += fabsf(s.y * (a.y - g[f].y));
            acc[f] += fabsf(s.z * (a.z - g[f].z));
            acc[f] += fabsf(s.w * (a.w - g[f].w));
        }
    }

    // Warp shuffle reduce each of the 12 accumulators, then combine warps.
    const int lane = threadIdx.x & 31;
    const int warp = threadIdx.x >> 5;
#pragma unroll
    for (int f = 0; f < NF; ++f) {
        float v = acc[f];
#pragma unroll
        for (int o = 16; o > 0; o >>= 1)
            v += __shfl_down_sync(0xffffffffu, v, o);
        acc[f] = v;   // valid on lane 0
    }

    __shared__ float sh[TPB / 32][NF];
    if (lane == 0) {
#pragma unroll
        for (int f = 0; f < NF; ++f) sh[warp][f] = acc[f];
    }
    __syncthreads();
    if (threadIdx.x < NF) {
        const int f = threadIdx.x;
        float s = 0.f;
#pragma unroll
        for (int w = 0; w < TPB / 32; ++w) s += sh[w][f];
        g_part[(b * NF + f) * BPB + blockIdx.x] = s;
    }

    // ---- last-block-done: run selection in whichever block finishes last ---
    __shared__ bool amLast;
    if (threadIdx.x == 0) {
        __threadfence();
        amLast = (atomicAdd(&g_cnt, 1u) == (unsigned)(BPB * BZ) - 1u);
    }
    __syncthreads();
    if (amLast) select_tail();
}

// ---------------------------------------------------------------------------
// Kernel 2: gather-copy. Batch 8 independent streaming loads into registers,
// then 8 write-back stores. Block chunk = 2048 float4, divides CHW4.
// ---------------------------------------------------------------------------
#define CPT 8
__global__ __launch_bounds__(TPB) void k_copy(const float* __restrict__ xf,
                                              float* __restrict__ out) {
    const long long q0 = (long long)blockIdx.x * (TPB * CPT);
    const int r     = (int)(q0 >> 19);      // output row 0..7, constant per block
    const int b     = r & (BZ - 1);
    const int which = r >> 2;
    const int f     = g_sel[which * BZ + b];

    const float4* __restrict__ src = (const float4*)(xf + ((size_t)f * BZ + b) * CHW);
    float4* __restrict__ dst = (float4*)out;

    const int n0 = (int)(q0 & (CHW4 - 1)) + threadIdx.x;
    float4 v[CPT];
#pragma unroll
    for (int c = 0; c < CPT; ++c) v[c] = __ldcs(&src[n0 + c * TPB]);
#pragma unroll
    for (int c = 0; c < CPT; ++c) dst[q0 + threadIdx.x + c * TPB] = v[c];
}

// ---------------------------------------------------------------------------
extern "C" void kernel_launch(void* const* d_in, const int* in_sizes, int n_in,
                              void* d_out, int out_size) {
    const float* x   = (const float*)d_in[0];   // [4,32,256,256]
    const float* xf  = (const float*)d_in[1];   // [48,32,256,256]
    const float* sal = (const float*)d_in[2];   // [4,1,256,256]
    float*       out = (float*)d_out;           // [8,32,256,256]

    dim3 gridR(BPB, BZ);
    k_reduce<<<gridR, TPB>>>(x, xf, sal);
    const unsigned blocksC = (unsigned)((2LL * BZ * CHW4) / (TPB * CPT)); // 2048
    k_copy<<<blocksC, TPB>>>(xf, out);
}